// round 10
// baseline (speedup 1.0000x reference)
#include <cuda_runtime.h>

// Depthwise 3x3 lateral conv (center tap excluded) + residual, NHWC f32.
// x: [32,56,56,256], kernel: [3,3,256], out: [32,56,56,256]
//
// R10: R8 structure (HR=4 x WR=4 float2 tile, interior fast path) + L2
// eviction policy via createpolicy + .L2::cache_hint (the static
// .L2::evict_last modifier is width-restricted on this ptxas; cache_hint
// is not). Loads: evict_last -> pin x (103MB) in the 126MB L2 across graph
// replays. Stores: evict_first -> write traffic doesn't evict x.

#define H 56
#define W 56
#define C2 128        // channels as float2
#define HR 4
#define WR 4

__device__ __forceinline__ unsigned long long mk_policy_evict_last() {
    unsigned long long pol;
    asm("createpolicy.fractional.L2::evict_last.b64 %0, 1.0;" : "=l"(pol));
    return pol;
}

__device__ __forceinline__ unsigned long long mk_policy_evict_first() {
    unsigned long long pol;
    asm("createpolicy.fractional.L2::evict_first.b64 %0, 1.0;" : "=l"(pol));
    return pol;
}

__device__ __forceinline__ float2 ld_el(const float2* p, unsigned long long pol) {
    float2 v;
    asm("ld.global.nc.L2::cache_hint.v2.f32 {%0,%1}, [%2], %3;"
        : "=f"(v.x), "=f"(v.y) : "l"(p), "l"(pol));
    return v;
}

__device__ __forceinline__ void st_ef(float2* p, float2 v, unsigned long long pol) {
    asm volatile("st.global.L2::cache_hint.v2.f32 [%0], {%1,%2}, %3;"
                 :: "l"(p), "f"(v.x), "f"(v.y), "l"(pol) : "memory");
}

__device__ __forceinline__ void f2fma(float2& a, float2 v, float2 k) {
    a.x = fmaf(v.x, k.x, a.x);
    a.y = fmaf(v.y, k.y, a.y);
}

__global__ __launch_bounds__(128, 4) void contour_kernel(
    const float* __restrict__ x,
    const float* __restrict__ kern,
    float* __restrict__ out)
{
    const int c2 = threadIdx.x;              // 0..127 (2 channels)
    const int wb = blockIdx.x * WR;          // 0,4,...,52
    const int hb = blockIdx.y * HR;          // 0,4,...,52
    const int b  = blockIdx.z;

    const unsigned long long pol_ld = mk_policy_evict_last();
    const unsigned long long pol_st = mk_policy_evict_first();

    const float2* __restrict__ xin = reinterpret_cast<const float2*>(x);
    const float2* __restrict__ k2  = reinterpret_cast<const float2*>(kern);
    float2* __restrict__ o = reinterpret_cast<float2*>(out);

    // 8 lateral taps -> registers (center excluded; residual = center add)
    float2 kreg[8];
    #pragma unroll
    for (int t = 0; t < 8; t++) {
        const int tap = t + (t >= 4 ? 1 : 0);
        kreg[t] = k2[tap * C2 + c2];
    }

    const int img = b * (H * W * C2);

    float2 acc[HR][WR];
    #pragma unroll
    for (int r = 0; r < HR; r++)
        #pragma unroll
        for (int j = 0; j < WR; j++)
            acc[r][j] = make_float2(0.f, 0.f);

    const bool interior = (hb >= 1) & (hb + HR + 1 <= H) & (wb >= 1) & (wb + WR + 1 <= W);

    if (interior) {
        const float2* __restrict__ p =
            xin + img + ((hb - 1) * W + (wb - 1)) * C2 + c2;

        #pragma unroll
        for (int ih = 0; ih < HR + 2; ih++) {
            float2 v[WR + 2];
            #pragma unroll
            for (int j = 0; j < WR + 2; j++)
                v[j] = ld_el(p + (ih * W + j) * C2, pol_ld);

            #pragma unroll
            for (int r = 0; r < HR; r++) {
                const int kh = ih - r;
                if (kh < 0 || kh > 2) continue;
                #pragma unroll
                for (int dw = 0; dw < 3; dw++) {
                    const bool is_center = (kh == 1 && dw == 1);
                    const int lin = kh * 3 + dw;
                    const int t = lin - (lin > 4 ? 1 : 0);
                    #pragma unroll
                    for (int j = 0; j < WR; j++) {
                        if (is_center) {
                            acc[r][j].x += v[j + 1].x;   // residual
                            acc[r][j].y += v[j + 1].y;
                        } else {
                            f2fma(acc[r][j], v[j + dw], kreg[t]);
                        }
                    }
                }
            }
        }
    } else {
        #pragma unroll
        for (int ih = 0; ih < HR + 2; ih++) {
            const int row = hb - 1 + ih;
            if (row < 0 || row >= H) continue;
            const int rb = img + row * (W * C2) + c2;

            float2 v[WR + 2];
            #pragma unroll
            for (int j = 0; j < WR + 2; j++) {
                const int col = wb - 1 + j;
                v[j] = ((unsigned)col < (unsigned)W) ? ld_el(xin + rb + col * C2, pol_ld)
                                                     : make_float2(0.f, 0.f);
            }

            #pragma unroll
            for (int r = 0; r < HR; r++) {
                const int kh = ih - r;
                if (kh < 0 || kh > 2) continue;
                #pragma unroll
                for (int dw = 0; dw < 3; dw++) {
                    const bool is_center = (kh == 1 && dw == 1);
                    const int lin = kh * 3 + dw;
                    const int t = lin - (lin > 4 ? 1 : 0);
                    #pragma unroll
                    for (int j = 0; j < WR; j++) {
                        if (is_center) {
                            acc[r][j].x += v[j + 1].x;
                            acc[r][j].y += v[j + 1].y;
                        } else {
                            f2fma(acc[r][j], v[j + dw], kreg[t]);
                        }
                    }
                }
            }
        }
    }

    #pragma unroll
    for (int r = 0; r < HR; r++) {
        const int rb = img + (hb + r) * (W * C2) + c2;
        #pragma unroll
        for (int j = 0; j < WR; j++)
            st_ef(o + rb + (wb + j) * C2, acc[r][j], pol_st);
    }
}

extern "C" void kernel_launch(void* const* d_in, const int* in_sizes, int n_in,
                              void* d_out, int out_size)
{
    const float* x    = (const float*)d_in[0];   // [32,56,56,256]
    const float* kern = (const float*)d_in[1];   // [3,3,256]
    float* outp       = (float*)d_out;

    dim3 block(C2, 1, 1);            // 128 threads
    dim3 grid(W / WR, H / HR, 32);   // 14 x 14 x 32 = 6272 blocks
    contour_kernel<<<grid, block>>>(x, kern, outp);
}

// round 11
// speedup vs baseline: 1.0582x; 1.0582x over previous
#include <cuda_runtime.h>

// Depthwise 3x3 lateral conv (center tap excluded) + residual, NHWC f32.
// x: [32,56,56,256], kernel: [3,3,256], out: [32,56,56,256]
//
// R11: persistent grid-stride version of R8. Grid = 592 blocks (148 SMs x
// occ 4); each block loops over ~10.6 tiles in the same x-fastest order the
// hardware wave scheduler would use (preserves halo L2 locality), removing
// ~9 wave transitions (~1.2us each per the B300 T_chip model) and
// amortizing tap loads once per block. Per-tile math identical to R8:
// HR=4 x WR=4 float2 tile, interior fast path, taps in registers,
// residual folded as center add.

#define H 56
#define W 56
#define C2 128        // channels as float2
#define HR 4
#define WR 4
#define TX (W / WR)   // 14 tiles in w
#define TY (H / HR)   // 14 tiles in h
#define TB 32         // batches
#define NTILES (TX * TY * TB)   // 6272
#define NBLOCKS 592   // 148 SMs x 4 CTAs

__device__ __forceinline__ void f2fma(float2& a, float2 v, float2 k) {
    a.x = fmaf(v.x, k.x, a.x);
    a.y = fmaf(v.y, k.y, a.y);
}

__global__ __launch_bounds__(128, 4) void contour_kernel(
    const float* __restrict__ x,
    const float* __restrict__ kern,
    float* __restrict__ out)
{
    const int c2 = threadIdx.x;              // 0..127 (2 channels)

    const float2* __restrict__ xin = reinterpret_cast<const float2*>(x);
    const float2* __restrict__ k2  = reinterpret_cast<const float2*>(kern);
    float2* __restrict__ o = reinterpret_cast<float2*>(out);

    // 8 lateral taps -> registers ONCE per block (c2 invariant across tiles)
    float2 kreg[8];
    #pragma unroll
    for (int t = 0; t < 8; t++) {
        const int tap = t + (t >= 4 ? 1 : 0);
        kreg[t] = k2[tap * C2 + c2];
    }

    for (int tile = blockIdx.x; tile < NTILES; tile += NBLOCKS) {
        // decompose: x fastest, then y, then batch (mirrors wave order)
        const int xb = tile % TX;
        const int yb = (tile / TX) % TY;
        const int b  = tile / (TX * TY);

        const int wb = xb * WR;
        const int hb = yb * HR;
        const int img = b * (H * W * C2);

        float2 acc[HR][WR];
        #pragma unroll
        for (int r = 0; r < HR; r++)
            #pragma unroll
            for (int j = 0; j < WR; j++)
                acc[r][j] = make_float2(0.f, 0.f);

        const bool interior = (hb >= 1) & (hb + HR + 1 <= H) &
                              (wb >= 1) & (wb + WR + 1 <= W);

        if (interior) {
            const float2* __restrict__ p =
                xin + img + ((hb - 1) * W + (wb - 1)) * C2 + c2;

            #pragma unroll
            for (int ih = 0; ih < HR + 2; ih++) {
                float2 v[WR + 2];
                #pragma unroll
                for (int j = 0; j < WR + 2; j++)
                    v[j] = p[(ih * W + j) * C2];

                #pragma unroll
                for (int r = 0; r < HR; r++) {
                    const int kh = ih - r;
                    if (kh < 0 || kh > 2) continue;
                    #pragma unroll
                    for (int dw = 0; dw < 3; dw++) {
                        const bool is_center = (kh == 1 && dw == 1);
                        const int lin = kh * 3 + dw;
                        const int t = lin - (lin > 4 ? 1 : 0);
                        #pragma unroll
                        for (int j = 0; j < WR; j++) {
                            if (is_center) {
                                acc[r][j].x += v[j + 1].x;   // residual
                                acc[r][j].y += v[j + 1].y;
                            } else {
                                f2fma(acc[r][j], v[j + dw], kreg[t]);
                            }
                        }
                    }
                }
            }
        } else {
            #pragma unroll
            for (int ih = 0; ih < HR + 2; ih++) {
                const int row = hb - 1 + ih;
                if (row < 0 || row >= H) continue;
                const int rb = img + row * (W * C2) + c2;

                float2 v[WR + 2];
                #pragma unroll
                for (int j = 0; j < WR + 2; j++) {
                    const int col = wb - 1 + j;
                    v[j] = ((unsigned)col < (unsigned)W) ? xin[rb + col * C2]
                                                         : make_float2(0.f, 0.f);
                }

                #pragma unroll
                for (int r = 0; r < HR; r++) {
                    const int kh = ih - r;
                    if (kh < 0 || kh > 2) continue;
                    #pragma unroll
                    for (int dw = 0; dw < 3; dw++) {
                        const bool is_center = (kh == 1 && dw == 1);
                        const int lin = kh * 3 + dw;
                        const int t = lin - (lin > 4 ? 1 : 0);
                        #pragma unroll
                        for (int j = 0; j < WR; j++) {
                            if (is_center) {
                                acc[r][j].x += v[j + 1].x;
                                acc[r][j].y += v[j + 1].y;
                            } else {
                                f2fma(acc[r][j], v[j + dw], kreg[t]);
                            }
                        }
                    }
                }
            }
        }

        #pragma unroll
        for (int r = 0; r < HR; r++) {
            const int rb = img + (hb + r) * (W * C2) + c2;
            #pragma unroll
            for (int j = 0; j < WR; j++)
                o[rb + (wb + j) * C2] = acc[r][j];
        }
    }
}

extern "C" void kernel_launch(void* const* d_in, const int* in_sizes, int n_in,
                              void* d_out, int out_size)
{
    const float* x    = (const float*)d_in[0];   // [32,56,56,256]
    const float* kern = (const float*)d_in[1];   // [3,3,256]
    float* outp       = (float*)d_out;

    dim3 block(C2, 1, 1);            // 128 threads
    dim3 grid(NBLOCKS, 1, 1);        // 592 persistent blocks
    contour_kernel<<<grid, block>>>(x, kern, outp);
}